// round 5
// baseline (speedup 1.0000x reference)
#include <cuda_runtime.h>

// ContrastiveLoss (discriminative loss), fixed shapes:
//   input_:  (4, 32, 512, 512) float32, channel-major
//   target:  (4, 1, 512, 512)  int32, labels in [0, 100)
// Output: scalar float32.

#define BB 4
#define CC 32
#define HW 262144
#define NI 100
#define PITCH 33              // bank(l*33+c) = (l+c)%32 -> conflict-free rows
#define ROWS 103              // 100 real + 3 dummy rows for dedup redirect
#define TSZ (ROWS * PITCH)    // 3399 floats
#define NBLK 256              // pass1 blocks per batch
#define P2 36                 // mean row pitch (16B aligned)
#define DVAR 0.75f
#define REP 4.0f              // 2 * DELTA_DIST

__device__ float g_part[BB * NBLK * (NI * PITCH)];  // raw per-block tables (13.5MB)
__device__ float g_mean[BB * NI * P2];              // means + inv-count

// ---------------------------------------------------------------------------
// Branchless 4-pixel RMW into the warp-private table (validated in R4).
// Duplicates merge into the earliest slot; freed slots redirect to dummy rows
// 100..102 so the 4 addresses are always distinct -> batched, no serialization.
__device__ __forceinline__ void rmw4(float* __restrict__ T, int lane,
                                     int l0, int l1, int l2, int l3,
                                     float v0, float v1, float v2, float v3) {
    float c0 = 1.0f, c1 = 1.0f, c2 = 1.0f, c3 = 1.0f;
    if (l1 == l0) { v0 += v1; c0 += c1; v1 = 0.0f; c1 = 0.0f; l1 = NI; }
    if (l2 == l0) { v0 += v2; c0 += c2; v2 = 0.0f; c2 = 0.0f; l2 = NI + 1; }
    else if (l2 == l1) { v1 += v2; c1 += c2; v2 = 0.0f; c2 = 0.0f; l2 = NI + 1; }
    if (l3 == l0) { v0 += v3; c0 += c3; v3 = 0.0f; c3 = 0.0f; l3 = NI + 2; }
    else if (l3 == l1) { v1 += v3; c1 += c3; v3 = 0.0f; c3 = 0.0f; l3 = NI + 2; }
    else if (l3 == l2) { v2 += v3; c2 += c3; v3 = 0.0f; c3 = 0.0f; l3 = NI + 2; }

    const int a0 = l0 * PITCH + lane, a1 = l1 * PITCH + lane;
    const int a2 = l2 * PITCH + lane, a3 = l3 * PITCH + lane;
    const float t0 = T[a0], t1 = T[a1], t2 = T[a2], t3 = T[a3];
    T[a0] = t0 + v0;  T[a1] = t1 + v1;  T[a2] = t2 + v2;  T[a3] = t3 + v3;

    if (lane < 4) {    // counts: 4 lanes, 4 distinct rows post-dedup
        const int   ll = (lane == 0) ? l0 : (lane == 1) ? l1 : (lane == 2) ? l2 : l3;
        const float cc = (lane == 0) ? c0 : (lane == 1) ? c1 : (lane == 2) ? c2 : c3;
        T[ll * PITCH + 32] += cc;
    }
}

// ---------------------------------------------------------------------------
// Pass 1: per-label sums+counts into warp-private tables, flushed as raw
// per-block partials (NO atomics). Coalesced loads, smem-staged transpose.
// Grid (256, 4), block 64 (2 warps), 512 px/warp in 16 chunks of 32.
__global__ void __launch_bounds__(64) k_pass1(const float* __restrict__ in,
                                              const int* __restrict__ tgt) {
    __shared__ __align__(16) float tab[2][TSZ];        // 27.2 KB
    __shared__ __align__(16) float tile[2][32 * PITCH];// 8.45 KB
    __shared__ __align__(16) int   lab[2][32];

    const int b    = blockIdx.y;
    const int warp = threadIdx.x >> 5;
    const int lane = threadIdx.x & 31;
    float* T  = tab[warp];
    float* TL = tile[warp];
    int*   L  = lab[warp];

    for (int i = threadIdx.x; i < 2 * TSZ; i += 64) (&tab[0][0])[i] = 0.0f;
    __syncthreads();

    const int*   tb  = tgt + (size_t)b * HW;
    const float* inb = in  + (size_t)b * CC * HW;
    const int base = (blockIdx.x * 2 + warp) * 512;

    for (int ch = 0; ch < 16; ++ch) {
        const int p0 = base + ch * 32;
        if (lane < 8) ((int4*)L)[lane] = ((const int4*)(tb + p0))[lane];
        // stage: coalesced LDG per channel row -> transposed smem tile
#pragma unroll
        for (int c = 0; c < CC; ++c)
            TL[lane * PITCH + c] = inb[(size_t)c * HW + p0 + lane];
        __syncwarp();

#pragma unroll
        for (int g = 0; g < 8; ++g) {
            const int4 Lg = *(const int4*)(L + g * 4);   // broadcast LDS.128
            const float v0 = TL[(4 * g + 0) * PITCH + lane];
            const float v1 = TL[(4 * g + 1) * PITCH + lane];
            const float v2 = TL[(4 * g + 2) * PITCH + lane];
            const float v3 = TL[(4 * g + 3) * PITCH + lane];
            rmw4(T, lane, Lg.x, Lg.y, Lg.z, Lg.w, v0, v1, v2, v3);
        }
        __syncwarp();
    }
    __syncthreads();

    // flush: combine 2 warp tables, plain coalesced stores (rows 0..99 only)
    float* dst = g_part + (size_t)(b * NBLK + blockIdx.x) * (NI * PITCH);
    for (int i = threadIdx.x; i < NI * PITCH; i += 64)
        dst[i] = tab[0][i] + tab[1][i];
}

// ---------------------------------------------------------------------------
// Reduce 256 partials/batch -> g_mean (means + inv count). Grid (25, 4),
// block 256: each block owns 4 labels (144 outputs incl. padding).
__global__ void __launch_bounds__(256) k_reduce(float* __restrict__ out) {
    __shared__ float sraw[4 * P2];
    const int b = blockIdx.y, l0 = blockIdx.x * 4;
    const int t = threadIdx.x;

    if (t < 4 * P2) {
        const int l = l0 + t / P2, c = t % P2;
        float s = 0.0f;
        if (c < 33) {
            const float* src = g_part + (size_t)(b * NBLK) * (NI * PITCH) + l * PITCH + c;
#pragma unroll 8
            for (int k = 0; k < NBLK; ++k) s += src[(size_t)k * (NI * PITCH)];
        }
        sraw[t] = s;
    }
    __syncthreads();
    if (t < 4 * P2) {
        const int c = t % P2;
        const float cnt = sraw[(t / P2) * P2 + 32];
        float v = 0.0f;
        if (c < 32)       v = sraw[t] / cnt;
        else if (c == 32) v = 1.0f / cnt;
        g_mean[b * (NI * P2) + l0 * P2 + t] = v;
    }
    if (b == 0 && blockIdx.x == 0 && t == 0) out[0] = 0.0f;
}

// ---------------------------------------------------------------------------
// Pass 2: variance term (blocks 0..31/batch, 8192 px each) + distance and
// regularizer terms (block 32). Means: float4 LDS gathers, pitch 36.
__global__ void __launch_bounds__(1024) k_var(const float* __restrict__ in,
                                              const int* __restrict__ tgt,
                                              float* __restrict__ out) {
    __shared__ __align__(16) float sm[NI * P2];   // 14.4 KB
    __shared__ float red[32];

    const int b = blockIdx.y;
    for (int i = threadIdx.x; i < NI * P2; i += 1024)
        sm[i] = g_mean[b * (NI * P2) + i];
    __syncthreads();

    float acc = 0.0f;
    if (blockIdx.x < 32) {
        const float* inb = in  + (size_t)b * CC * HW;
        const int*   tb  = tgt + (size_t)b * HW;
        const int p0 = blockIdx.x * 8192 + threadIdx.x;
#pragma unroll
        for (int k = 0; k < 8; ++k) {
            const int p = p0 + k * 1024;
            const int l = tb[p];
            const float4* m4 = (const float4*)(sm + l * P2);
            float d2 = 0.0f;
#pragma unroll
            for (int q = 0; q < 8; ++q) {
                const float4 mm = m4[q];
                const float vx = inb[(size_t)(4 * q + 0) * HW + p] - mm.x;
                const float vy = inb[(size_t)(4 * q + 1) * HW + p] - mm.y;
                const float vz = inb[(size_t)(4 * q + 2) * HW + p] - mm.z;
                const float vw = inb[(size_t)(4 * q + 3) * HW + p] - mm.w;
                d2 = fmaf(vx, vx, d2); d2 = fmaf(vy, vy, d2);
                d2 = fmaf(vz, vz, d2); d2 = fmaf(vw, vw, d2);
            }
            const float r = sqrtf(d2);
            const float h = fmaxf(r - DVAR, 0.0f);
            acc = fmaf(h * h, sm[l * P2 + 32], acc);
        }
        acc *= (1.0f / (NI * BB));                          // ALPHA = 1
    } else {
        float accd = 0.0f, accr = 0.0f;
        for (int idx = threadIdx.x; idx < NI * NI; idx += 1024) {
            const int i = idx / NI, j = idx - i * NI;
            if (i == j) continue;
            float d2 = 0.0f;
#pragma unroll
            for (int q = 0; q < 8; ++q) {
                const float4 a = *(const float4*)(sm + i * P2 + 4 * q);
                const float4 c = *(const float4*)(sm + j * P2 + 4 * q);
                const float vx = a.x - c.x, vy = a.y - c.y;
                const float vz = a.z - c.z, vw = a.w - c.w;
                d2 = fmaf(vx, vx, d2); d2 = fmaf(vy, vy, d2);
                d2 = fmaf(vz, vz, d2); d2 = fmaf(vw, vw, d2);
            }
            const float d = (d2 > 0.0f) ? sqrtf(d2) : 1.0f;
            const float h = fmaxf(REP - d, 0.0f);
            accd = fmaf(h, h, accd);
        }
        if (threadIdx.x < NI) {
            const int i = threadIdx.x;
            float n2 = 0.0f;
#pragma unroll
            for (int q = 0; q < 8; ++q) {
                const float4 a = *(const float4*)(sm + i * P2 + 4 * q);
                n2 = fmaf(a.x, a.x, n2); n2 = fmaf(a.y, a.y, n2);
                n2 = fmaf(a.z, a.z, n2); n2 = fmaf(a.w, a.w, n2);
            }
            accr = sqrtf(n2);
        }
        acc = accd * (1.0f / (NI * (NI - 1) * BB))          // BETA = 1
            + accr * (0.001f / (NI * BB));                  // GAMMA = 0.001
    }

#pragma unroll
    for (int o = 16; o > 0; o >>= 1) acc += __shfl_down_sync(0xffffffffu, acc, o);
    if ((threadIdx.x & 31) == 0) red[threadIdx.x >> 5] = acc;
    __syncthreads();
    if (threadIdx.x < 32) {
        float v = red[threadIdx.x];
#pragma unroll
        for (int o = 16; o > 0; o >>= 1) v += __shfl_down_sync(0xffffffffu, v, o);
        if (threadIdx.x == 0) atomicAdd(out, v);
    }
}

// ---------------------------------------------------------------------------
extern "C" void kernel_launch(void* const* d_in, const int* in_sizes, int n_in,
                              void* d_out, int out_size) {
    const float* in  = (const float*)d_in[0];
    const int*   tgt = (const int*)d_in[1];
    float* out = (float*)d_out;

    dim3 g1(NBLK, BB);
    k_pass1<<<g1, 64>>>(in, tgt);
    dim3 gr(25, BB);
    k_reduce<<<gr, 256>>>(out);
    dim3 g2(33, BB);
    k_var<<<g2, 1024>>>(in, tgt, out);
}

// round 6
// speedup vs baseline: 1.2345x; 1.2345x over previous
#include <cuda_runtime.h>

// ContrastiveLoss (discriminative loss), fixed shapes:
//   input_:  (4, 32, 512, 512) float32, channel-major
//   target:  (4, 1, 512, 512)  int32, labels in [0, 100)
// Output: scalar float32.

#define BB 4
#define CC 32
#define HW 262144
#define NI 100
#define NBLK 256              // pass1 blocks per batch
#define PSZ 3300              // per-block partial: 100*32 sums + 100 counts
#define MEANSZ 3536           // 32*104 meansT + 104 msq + 104 invc
#define MP 104                // transposed means pitch
#define DVAR 0.75f
#define REP 4.0f              // 2 * DELTA_DIST

__device__ float g_part[BB * NBLK * PSZ];   // 13.5 MB raw per-block tables
__device__ float g_mean[BB * MEANSZ];       // meansT + ||m||^2 + 1/cnt

// ---------------------------------------------------------------------------
// Pass 1: per-label channel sums + counts into warp-private smem tables.
// No dedup needed: same-warp smem RMWs to aliasing addresses execute in
// order in the LSU. lane = channel -> table pitch 32 is conflict-free.
// Grid (256, 4), block 64 (2 warps), 512 px/warp in 16 chunks of 32.
__global__ void __launch_bounds__(64) k_pass1(const float* __restrict__ in,
                                              const int* __restrict__ tgt) {
    __shared__ float tab[2][NI * 32];              // 25.6 KB
    __shared__ float cnt[2][104];                  // 0.8 KB
    __shared__ float tile[2][32 * 33];             // 8.45 KB, [px][c] pitch 33
    __shared__ __align__(16) int lab[2][32];

    const int b    = blockIdx.y;
    const int warp = threadIdx.x >> 5;
    const int lane = threadIdx.x & 31;
    float* T  = tab[warp];
    float* Cn = cnt[warp];
    float* TL = tile[warp];
    int*   L  = lab[warp];

    for (int i = threadIdx.x; i < 2 * NI * 32; i += 64) (&tab[0][0])[i] = 0.0f;
    for (int i = threadIdx.x; i < 2 * 104; i += 64)     (&cnt[0][0])[i] = 0.0f;
    __syncthreads();

    const int*   tb  = tgt + (size_t)b * HW;
    const float* inb = in  + (size_t)b * CC * HW;
    const int base = (blockIdx.x * 2 + warp) * 512;

    for (int ch = 0; ch < 16; ++ch) {
        const int p0 = base + ch * 32;
        if (lane < 8) ((int4*)L)[lane] = ((const int4*)(tb + p0))[lane];
        // stage: coalesced LDG (lane = pixel), transposed store, pitch 33
        const float* src = inb + p0 + lane;
#pragma unroll
        for (int c = 0; c < CC; ++c)
            TL[lane * 33 + c] = src[(size_t)c * HW];
        __syncwarp();

        // consume: lane = channel, serial over 32 pixels (LSU keeps order)
#pragma unroll
        for (int j = 0; j < 32; ++j) {
            const int   l = L[j];              // broadcast LDS
            const float v = TL[j * 33 + lane]; // conflict-free LDS
            T[l * 32 + lane] += v;             // LDS+FADD+STS, in-order safe
            if (lane == 0) Cn[l] += 1.0f;
        }
        __syncwarp();
    }
    __syncthreads();

    // flush raw partials (plain coalesced stores, no atomics)
    float* dst = g_part + (size_t)(b * NBLK + blockIdx.x) * PSZ;
    for (int i = threadIdx.x; i < NI * 32; i += 64)
        dst[i] = tab[0][i] + tab[1][i];
    for (int i = threadIdx.x; i < NI; i += 64)
        dst[NI * 32 + i] = cnt[0][i] + cnt[1][i];
}

// ---------------------------------------------------------------------------
// Reduce 256 partials/batch -> transposed means + ||m||^2 + 1/cnt.
// Grid (100, 4) [block = one label], 160 threads: groups 0-3 sum channel
// partials over k-quarters, group 4 sums counts. Also zeroes out[0].
__global__ void __launch_bounds__(160) k_reduce(float* __restrict__ out) {
    __shared__ float ssum[4][32];
    __shared__ float scnt;

    const int b = blockIdx.y, l = blockIdx.x;
    const int t = threadIdx.x, g = t >> 5, lane = t & 31;
    const float* base = g_part + (size_t)b * NBLK * PSZ;

    if (g < 4) {
        float s = 0.0f;
        const float* p = base + l * 32 + lane;
#pragma unroll 8
        for (int k = g * 64; k < g * 64 + 64; ++k) s += p[(size_t)k * PSZ];
        ssum[g][lane] = s;
    } else {
        float s = 0.0f;
        const float* p = base + NI * 32 + l;
#pragma unroll
        for (int i = 0; i < 8; ++i) s += p[(size_t)(lane * 8 + i) * PSZ];
#pragma unroll
        for (int o = 16; o > 0; o >>= 1) s += __shfl_down_sync(0xffffffffu, s, o);
        if (lane == 0) scnt = s;
    }
    __syncthreads();

    if (t < 32) {
        const float cntv = scnt;
        const float m = (ssum[0][t] + ssum[1][t] + ssum[2][t] + ssum[3][t]) / cntv;
        g_mean[b * MEANSZ + t * MP + l] = m;           // transposed: [c][l]
        float q = m * m;
#pragma unroll
        for (int o = 16; o > 0; o >>= 1) q += __shfl_down_sync(0xffffffffu, q, o);
        if (t == 0) {
            g_mean[b * MEANSZ + 32 * MP + l]       = q;           // ||m||^2
            g_mean[b * MEANSZ + 32 * MP + 104 + l] = 1.0f / cntv; // 1/cnt
        }
    }
    if (b == 0 && l == 0 && t == 33) out[0] = 0.0f;
}

// ---------------------------------------------------------------------------
// Pass 2: variance via ||f-m||^2 = ||f||^2 - 2 f.m + ||m||^2 (scalar LDS
// gathers from transposed means). Blocks 0..63 per batch stream 4096 px each;
// block 64 does the pairwise-distance + regularizer terms.
__global__ void __launch_bounds__(512) k_var(const float* __restrict__ in,
                                             const int* __restrict__ tgt,
                                             float* __restrict__ out) {
    __shared__ float sm[MEANSZ];     // 14.1 KB: meansT | msq | invc
    __shared__ float red[16];

    const int b = blockIdx.y;
    for (int i = threadIdx.x; i < MEANSZ; i += 512)
        sm[i] = g_mean[b * MEANSZ + i];
    __syncthreads();
    const float* s_msq  = sm + 32 * MP;
    const float* s_invc = sm + 32 * MP + 104;

    float acc = 0.0f;
    if (blockIdx.x < 64) {
        const float* inb = in  + (size_t)b * CC * HW;
        const int*   tb  = tgt + (size_t)b * HW;
        const int p0 = blockIdx.x * 4096 + threadIdx.x;
#pragma unroll
        for (int k = 0; k < 8; ++k) {
            const int p = p0 + k * 512;
            const int l = tb[p];
            const float* fp = inb + p;
            float f2 = 0.0f, fd = 0.0f;
#pragma unroll
            for (int c = 0; c < CC; ++c) {
                const float f = fp[(size_t)c * HW];
                const float m = sm[c * MP + l];
                f2 = fmaf(f, f, f2);
                fd = fmaf(f, m, fd);
            }
            const float d2 = fmaxf(f2 - 2.0f * fd + s_msq[l], 0.0f);
            const float r  = sqrtf(d2);
            const float h  = fmaxf(r - DVAR, 0.0f);
            acc = fmaf(h * h, s_invc[l], acc);
        }
        acc *= (1.0f / (NI * BB));                         // ALPHA = 1
    } else {
        // distance term: 9900 ordered pairs
        float accd = 0.0f, accr = 0.0f;
        for (int idx = threadIdx.x; idx < NI * NI; idx += 512) {
            const int i = idx / NI, j = idx - i * NI;
            if (i == j) continue;
            float d2 = 0.0f;
#pragma unroll
            for (int c = 0; c < CC; ++c) {
                const float v = sm[c * MP + i] - sm[c * MP + j];
                d2 = fmaf(v, v, d2);
            }
            const float d = (d2 > 0.0f) ? sqrtf(d2) : 1.0f;
            const float h = fmaxf(REP - d, 0.0f);
            accd = fmaf(h, h, accd);
        }
        if (threadIdx.x < NI) accr = sqrtf(s_msq[threadIdx.x]);
        acc = accd * (1.0f / (NI * (NI - 1) * BB))          // BETA = 1
            + accr * (0.001f / (NI * BB));                  // GAMMA = 0.001
    }

#pragma unroll
    for (int o = 16; o > 0; o >>= 1) acc += __shfl_down_sync(0xffffffffu, acc, o);
    if ((threadIdx.x & 31) == 0) red[threadIdx.x >> 5] = acc;
    __syncthreads();
    if (threadIdx.x < 32) {
        float v = (threadIdx.x < 16) ? red[threadIdx.x] : 0.0f;
#pragma unroll
        for (int o = 8; o > 0; o >>= 1) v += __shfl_down_sync(0xffffffffu, v, o);
        if (threadIdx.x == 0) atomicAdd(out, v);
    }
}

// ---------------------------------------------------------------------------
extern "C" void kernel_launch(void* const* d_in, const int* in_sizes, int n_in,
                              void* d_out, int out_size) {
    const float* in  = (const float*)d_in[0];
    const int*   tgt = (const int*)d_in[1];
    float* out = (float*)d_out;

    dim3 g1(NBLK, BB);
    k_pass1<<<g1, 64>>>(in, tgt);
    dim3 gr(NI, BB);
    k_reduce<<<gr, 160>>>(out);
    dim3 g2(65, BB);
    k_var<<<g2, 512>>>(in, tgt, out);
}